// round 7
// baseline (speedup 1.0000x reference)
#include <cuda_runtime.h>

namespace {
constexpr int kB = 128, kS = 2048, kD = 128, kNQ = 18;
constexpr int TS = 64;                  // s-tile size per CTA
constexpr int HALF_S = kS / 2;          // 1024 s per CTA
constexpr int NTILE = HALF_S / TS;      // 16
constexpr int THREADS = 256;
constexpr float SCALE = 0.08838834764831845f;  // 1/sqrt(128)

constexpr int XBUF_F4 = TS * 32;                 // 2048 float4 per x buffer
constexpr int SMEM_X = 2 * XBUF_F4 * 16;         // 65536 B (double buffer)
constexpr int SMEM_Q = kNQ * kD * 4;             // 9216 B
constexpr int SMEM_P = kNQ * TS * 4;             // 4608 B
constexpr int SMEM_L = 128;
constexpr int SMEM_M = HALF_S * 4;               // 4096 B mask
constexpr int SMEM_BYTES = SMEM_X + SMEM_Q + SMEM_P + SMEM_L + SMEM_M;  // ~83.6KB
constexpr int OUT_PER_B = kNQ * kD;              // 2304
}

// cross-CTA partials (2 CTAs per batch) + arrival counters (zero-init)
__device__ float    g_partP[kB][2][OUT_PER_B];
__device__ float    g_partL[kB][2][kNQ];
__device__ unsigned g_cnt[kB];

// ---- packed f32x2 helpers (B300 FFMA2 path, only reachable via PTX) ----
__device__ __forceinline__ unsigned long long pk2(float a, float b) {
    unsigned long long r;
    asm("mov.b64 %0, {%1,%2};" : "=l"(r) : "f"(a), "f"(b));
    return r;
}
__device__ __forceinline__ unsigned long long f2ma(unsigned long long a,
                                                   unsigned long long b,
                                                   unsigned long long c) {
    unsigned long long d;
    asm("fma.rn.f32x2 %0, %1, %2, %3;" : "=l"(d) : "l"(a), "l"(b), "l"(c));
    return d;
}
__device__ __forceinline__ float2 up2(unsigned long long v) {
    float lo, hi;
    asm("mov.b64 {%0,%1}, %2;" : "=f"(lo), "=f"(hi) : "l"(v));
    return make_float2(lo, hi);
}
__device__ __forceinline__ void cpa16(void* dst, const void* src) {
    unsigned a = (unsigned)__cvta_generic_to_shared(dst);
    asm volatile("cp.async.cg.shared.global [%0], [%1], 16;" :: "r"(a), "l"(src));
}

__global__ void __launch_bounds__(THREADS, 2)
AttentionPooling_main(const float* __restrict__ x,
                      const float* __restrict__ qe,
                      const int*   __restrict__ ques,
                      const int*   __restrict__ mask,
                      float*       __restrict__ out)
{
    extern __shared__ char smem[];
    float4* xb4  = reinterpret_cast<float4*>(smem);
    float*  q_sm = reinterpret_cast<float*>(smem + SMEM_X);
    float*  p_sm = q_sm + kNQ * kD;
    float*  l_sm = p_sm + kNQ * TS;
    int*    m_sm = reinterpret_cast<int*>(smem + SMEM_X + SMEM_Q + SMEM_P + SMEM_L);
    __shared__ int s_flag;

    const int t    = threadIdx.x;
    const int b    = blockIdx.x >> 1;
    const int half = blockIdx.x & 1;

    // ---- mask half -> smem (once, async): 1024 ints = 256 x 16B ----
    {
        const int* mb = mask + b * kS + half * HALF_S;
        cpa16(&m_sm[t * 4], mb + t * 4);
        asm volatile("cp.async.commit_group;");
    }

    // ---- gather q embeddings, pre-scaled; column-swizzled layout:
    // element d4=(dgrp*8+k) stored at col (k*4+dgrp) so phase-A octet reads
    // hit disjoint banks (kills the 4-way LDS conflict).
    for (int i = t; i < kNQ * 32; i += THREADS) {
        int j = i >> 5, d4 = i & 31;
        int qi = ques[b * kNQ + j];
        float4 v = reinterpret_cast<const float4*>(qe + qi * kD)[d4];
        v.x *= SCALE; v.y *= SCALE; v.z *= SCALE; v.w *= SCALE;
        int swz = ((d4 & 7) << 2) | (d4 >> 3);
        reinterpret_cast<float4*>(q_sm)[j * 32 + swz] = v;
    }
    if (t < kNQ) l_sm[t] = 0.0f;

    const float* xb = x + (size_t)b * kS * kD + (size_t)half * HALF_S * kD;

    // swizzled x tile store: col' = (d4 + s) & 31
    auto load_tile = [&](int tile, int buf) {
        const float* src = xb + tile * TS * kD;
        float4* dst = xb4 + buf * XBUF_F4;
        #pragma unroll
        for (int k = 0; k < 8; ++k) {
            int i = t + k * THREADS;              // 2048 float4s
            int s = i >> 5, d4 = i & 31;
            cpa16(&dst[s * 32 + ((d4 + s) & 31)], src + s * kD + d4 * 4);
        }
        asm volatile("cp.async.commit_group;");
    };

    load_tile(0, 0);

    // ---- phase A: 8 warps = qh(2) x sgrp(4 x 16s); lane = dgrp(4) x sslot(8)
    const int w     = t >> 5, lane = t & 31;
    const int qbA   = (w >> 2) * 9;
    const int sgrp  = w & 3;
    const int dgrp  = lane >> 3;
    const int sslot = lane & 7;
    const int srow  = sgrp * 16 + sslot;       // s(si) = srow + si*8, si in {0,1}
    const int sown  = srow + (dgrp & 1) * 8;   // s this lane stores (dgrp<2 only)

    // ---- phase B: 8 warps = qh(2) x slice(4 x 16s); lane = d4
    const int d4B = lane;
    const int qbB = ((t >> 5) & 1) * 9;
    const int slB = t >> 6;                    // 0..3

    unsigned long long acc[9][2];
    #pragma unroll
    for (int j = 0; j < 9; ++j) { acc[j][0] = 0ull; acc[j][1] = 0ull; }

    for (int tile = 0; tile < NTILE; ++tile) {
        const int buf = tile & 1;
        if (tile + 1 < NTILE) {
            load_tile(tile + 1, buf ^ 1);
            asm volatile("cp.async.wait_group 1;");
        } else {
            asm volatile("cp.async.wait_group 0;");
        }
        __syncthreads();

        // ================= phase A =================
        {
            const ulonglong2* xt =
                reinterpret_cast<const ulonglong2*>(xb4 + buf * XBUF_F4);
            const ulonglong2* qt = reinterpret_cast<const ulonglong2*>(q_sm);

            unsigned long long sc[9][2];
            #pragma unroll
            for (int j = 0; j < 9; ++j) { sc[j][0] = 0ull; sc[j][1] = 0ull; }

            #pragma unroll
            for (int k = 0; k < 8; ++k) {
                ulonglong2 xv[2];
                #pragma unroll
                for (int si = 0; si < 2; ++si) {
                    int s = srow + si * 8;
                    int c = (dgrp * 8 + k + s) & 31;
                    xv[si] = xt[s * 32 + c];
                }
                #pragma unroll
                for (int j = 0; j < 9; ++j) {
                    ulonglong2 qv = qt[(qbA + j) * 32 + k * 4 + dgrp];
                    #pragma unroll
                    for (int si = 0; si < 2; ++si) {
                        sc[j][si] = f2ma(xv[si].x, qv.x, sc[j][si]);
                        sc[j][si] = f2ma(xv[si].y, qv.y, sc[j][si]);
                    }
                }
            }

            const int mk = m_sm[tile * TS + sown];
            #pragma unroll
            for (int j = 0; j < 9; ++j) {
                float vs[2];
                #pragma unroll
                for (int si = 0; si < 2; ++si) {
                    float2 f = up2(sc[j][si]);
                    float v = f.x + f.y;
                    v += __shfl_xor_sync(0xffffffffu, v, 8);
                    v += __shfl_xor_sync(0xffffffffu, v, 16);
                    vs[si] = v;
                }
                float vsel = (dgrp & 1) ? vs[1] : vs[0];
                if (dgrp < 2)
                    p_sm[(qbA + j) * TS + sown] = mk ? __expf(vsel) : 0.0f;
            }
        }
        __syncthreads();

        // ---- row-sums of p into l (72 threads) ----
        if (t < kNQ * 4) {
            int q = t >> 2, w4 = t & 3;
            const float4* pr = reinterpret_cast<const float4*>(p_sm + q * TS + w4 * 16);
            float ss = 0.0f;
            #pragma unroll
            for (int k2 = 0; k2 < 4; ++k2) {
                float4 v = pr[k2];
                ss += (v.x + v.y) + (v.z + v.w);
            }
            atomicAdd(&l_sm[q], ss);
        }

        // ================= phase B =================
        {
            const ulonglong2* xt =
                reinterpret_cast<const ulonglong2*>(xb4 + buf * XBUF_F4);
            #pragma unroll
            for (int i = 0; i < 4; ++i) {
                const int s0 = slB * 16 + i * 4;
                ulonglong2 xq[4];
                #pragma unroll
                for (int k2 = 0; k2 < 4; ++k2)
                    xq[k2] = xt[(s0 + k2) * 32 + ((d4B + s0 + k2) & 31)];
                #pragma unroll
                for (int j = 0; j < 9; ++j) {
                    float4 pv = reinterpret_cast<const float4*>(
                        p_sm + (qbB + j) * TS)[slB * 4 + i];
                    unsigned long long p0 = pk2(pv.x, pv.x);
                    acc[j][0] = f2ma(xq[0].x, p0, acc[j][0]);
                    acc[j][1] = f2ma(xq[0].y, p0, acc[j][1]);
                    unsigned long long p1 = pk2(pv.y, pv.y);
                    acc[j][0] = f2ma(xq[1].x, p1, acc[j][0]);
                    acc[j][1] = f2ma(xq[1].y, p1, acc[j][1]);
                    unsigned long long p2 = pk2(pv.z, pv.z);
                    acc[j][0] = f2ma(xq[2].x, p2, acc[j][0]);
                    acc[j][1] = f2ma(xq[2].y, p2, acc[j][1]);
                    unsigned long long p3 = pk2(pv.w, pv.w);
                    acc[j][0] = f2ma(xq[3].x, p3, acc[j][0]);
                    acc[j][1] = f2ma(xq[3].y, p3, acc[j][1]);
                }
            }
        }
        __syncthreads();
    }

    // ---- reduce 4 slices x 2 q-halves through smem (reuse x area) ----
    float* red = reinterpret_cast<float*>(smem);   // 4*18*128*4 = 36864 B
    #pragma unroll
    for (int j = 0; j < 9; ++j) {
        float2 a = up2(acc[j][0]);
        float2 c = up2(acc[j][1]);
        reinterpret_cast<float4*>(red)[(slB * kNQ + (qbB + j)) * 32 + d4B] =
            make_float4(a.x, a.y, c.x, c.y);
    }
    __syncthreads();

    // ---- write per-CTA partials to global ----
    float* P = g_partP[b][half];
    for (int o = t; o < OUT_PER_B; o += THREADS) {
        float s0 = red[0 * OUT_PER_B + o] + red[1 * OUT_PER_B + o];
        float s1 = red[2 * OUT_PER_B + o] + red[3 * OUT_PER_B + o];
        P[o] = s0 + s1;
    }
    if (t < kNQ) g_partL[b][half][t] = l_sm[t];
    __syncthreads();

    // ---- last-arriver combines (deterministic order, counter self-resets) ----
    if (t == 0) {
        __threadfence();
        s_flag = (int)atomicAdd(&g_cnt[b], 1u);
    }
    __syncthreads();
    if (s_flag == 1) {
        __threadfence();   // acquire partner CTA's writes
        if (t < kNQ)
            l_sm[t] = 1.0f / (g_partL[b][0][t] + g_partL[b][1][t]);
        __syncthreads();
        const float* P0 = g_partP[b][0];
        const float* P1 = g_partP[b][1];
        float* ob = out + (size_t)b * OUT_PER_B;
        for (int o = t; o < OUT_PER_B; o += THREADS)
            ob[o] = (P0[o] + P1[o]) * l_sm[o >> 7];
        if (t == 0) g_cnt[b] = 0;   // reset for next graph replay
    }
}

extern "C" void kernel_launch(void* const* d_in, const int* in_sizes, int n_in,
                              void* d_out, int out_size) {
    const float* x    = (const float*)d_in[0];
    const float* qe   = (const float*)d_in[1];
    const int*   ques = (const int*)d_in[2];
    const int*   mask = (const int*)d_in[3];
    float* out = (float*)d_out;

    cudaFuncSetAttribute(AttentionPooling_main,
                         cudaFuncAttributeMaxDynamicSharedMemorySize, SMEM_BYTES);
    AttentionPooling_main<<<2 * kB, THREADS, SMEM_BYTES>>>(x, qe, ques, mask, out);
}

// round 9
// speedup vs baseline: 1.5732x; 1.5732x over previous
#include <cuda_runtime.h>
#include <cstdint>

namespace {
constexpr int kB = 128, kS = 2048, kD = 128, kNQ = 18;
constexpr int TS = 128, NTILE = kS / TS, THREADS = 256;
constexpr float SCALE = 0.08838834764831845f;   // 1/sqrt(128)
constexpr int XBUF_F4 = TS * 32;                // float4 per f32 x buffer

constexpr int XH_STRIDE = 272;                  // fp16 row pitch (128*2 + 16 pad)
constexpr int OFF_XH = 131072;                  // x fp16 [128][272]
constexpr int OFF_Q  = OFF_XH + TS * XH_STRIDE;            // 165888
constexpr int OFF_P  = OFF_Q + 32 * XH_STRIDE;             // 174592
constexpr int P_STRIDE = 136;                   // p row pitch in floats (128+8)
constexpr int OFF_M  = OFF_P + 32 * P_STRIDE * 4;          // 192000
constexpr int OFF_LR = OFF_M + kS * 4;                     // 200192
constexpr int OFF_LI = OFF_LR + 8 * 32 * 4;                // 201216
constexpr int SMEM_BYTES = OFF_LI + 128;                   // 201344
constexpr int OUT_PER_B = kNQ * kD;
}

// ---- packed f32x2 helpers (B300 FFMA2 path) ----
__device__ __forceinline__ unsigned long long pk2(float a, float b) {
    unsigned long long r; asm("mov.b64 %0, {%1,%2};" : "=l"(r) : "f"(a), "f"(b)); return r;
}
__device__ __forceinline__ unsigned long long f2ma(unsigned long long a,
                                                   unsigned long long b,
                                                   unsigned long long c) {
    unsigned long long d;
    asm("fma.rn.f32x2 %0, %1, %2, %3;" : "=l"(d) : "l"(a), "l"(b), "l"(c));
    return d;
}
__device__ __forceinline__ float2 up2(unsigned long long v) {
    float lo, hi; asm("mov.b64 {%0,%1}, %2;" : "=f"(lo), "=f"(hi) : "l"(v));
    return make_float2(lo, hi);
}
__device__ __forceinline__ void cpa16(void* dst, const void* src) {
    unsigned a = (unsigned)__cvta_generic_to_shared(dst);
    asm volatile("cp.async.cg.shared.global [%0], [%1], 16;" :: "r"(a), "l"(src));
}
__device__ __forceinline__ uint32_t pkh2(float hi_e, float lo_e) {
    uint32_t r;   // low half = fp16(lo_e) (first in memory), high = fp16(hi_e)
    asm("cvt.rn.f16x2.f32 %0, %1, %2;" : "=r"(r) : "f"(hi_e), "f"(lo_e));
    return r;
}

__global__ void __launch_bounds__(THREADS, 1)
AttentionPooling_main(const float* __restrict__ x,
                      const float* __restrict__ qe,
                      const int*   __restrict__ ques,
                      const int*   __restrict__ mask,
                      float*       __restrict__ out)
{
    extern __shared__ char smem[];
    float4* xb4  = reinterpret_cast<float4*>(smem);
    float*  p_sm = reinterpret_cast<float*>(smem + OFF_P);
    int*    m_sm = reinterpret_cast<int*>(smem + OFF_M);
    float*  lr   = reinterpret_cast<float*>(smem + OFF_LR);
    float*  li   = reinterpret_cast<float*>(smem + OFF_LI);

    const int t = threadIdx.x, w = t >> 5, lane = t & 31;
    const int b = blockIdx.x;
    const int wsb = w * 16;                        // warp's 16-s slice base
    const uint32_t sb = (uint32_t)__cvta_generic_to_shared(smem);

    // ---- async: mask + x tile 0 ----
    {
        const int* mb = mask + b * kS;
        cpa16(&m_sm[t * 4], mb + t * 4);
        cpa16(&m_sm[(t + 256) * 4], mb + (t + 256) * 4);
    }
    const float* xb = x + (size_t)b * kS * kD;
    auto load_tile = [&](int tile, int buf) {
        const float* src = xb + tile * TS * kD;
        float4* dst = xb4 + buf * XBUF_F4;
        #pragma unroll
        for (int k = 0; k < 16; ++k) {
            int i = t + k * THREADS;
            int s = i >> 5, d4 = i & 31;
            cpa16(&dst[s * 32 + ((d4 + s) & 31)], src + s * kD + d4 * 4);
        }
        asm volatile("cp.async.commit_group;");
    };
    load_tile(0, 0);

    // ---- q gather: fp16 [32 rows][272B], rows >= kNQ zeroed ----
    for (int i = t; i < 32 * 16; i += THREADS) {
        int j = i >> 4, c = i & 15;                 // row, 16B chunk (8 d each)
        uint4 pk = make_uint4(0u, 0u, 0u, 0u);
        if (j < kNQ) {
            int qi = ques[b * kNQ + j];
            const float4* qr = reinterpret_cast<const float4*>(qe + qi * kD);
            float4 v0 = qr[c * 2], v1 = qr[c * 2 + 1];
            pk.x = pkh2(v0.y * SCALE, v0.x * SCALE);
            pk.y = pkh2(v0.w * SCALE, v0.z * SCALE);
            pk.z = pkh2(v1.y * SCALE, v1.x * SCALE);
            pk.w = pkh2(v1.w * SCALE, v1.z * SCALE);
        }
        *reinterpret_cast<uint4*>(smem + OFF_Q + j * XH_STRIDE + c * 16) = pk;
    }
    __syncthreads();

    // ---- hoist q A-fragments: qa[m][k][4], loaded once ----
    uint32_t qa[2][8][4];
    {
        #pragma unroll
        for (int m = 0; m < 2; ++m)
            #pragma unroll
            for (int k = 0; k < 8; ++k) {
                uint32_t addr = sb + OFF_Q + (m * 16 + (lane & 15)) * XH_STRIDE
                              + (k * 2 + (lane >> 4)) * 16;
                asm volatile("ldmatrix.sync.aligned.m8n8.x4.shared.b16 {%0,%1,%2,%3},[%4];"
                    : "=r"(qa[m][k][0]), "=r"(qa[m][k][1]),
                      "=r"(qa[m][k][2]), "=r"(qa[m][k][3]) : "r"(addr));
            }
    }

    // phase B accumulators: all 18 q x 4 d (f32x2 pairs)
    unsigned long long acc[kNQ][2];
    #pragma unroll
    for (int j = 0; j < kNQ; ++j) { acc[j][0] = 0ull; acc[j][1] = 0ull; }
    float lsum[4] = {0.f, 0.f, 0.f, 0.f};
    const int cs = t & 127, cdh = t >> 7;          // convert: row, d-half

    for (int tile = 0; tile < NTILE; ++tile) {
        const int buf = tile & 1;
        asm volatile("cp.async.wait_group 0;" ::: "memory");
        __syncthreads();

        // ---- convert x f32 -> fp16 [128][272B] ----
        {
            const float4* xf = xb4 + buf * XBUF_F4 + (size_t)cs * 32;
            #pragma unroll
            for (int i = 0; i < 16; i += 2) {
                float4 a = xf[((cdh * 16 + i)     + cs) & 31];
                float4 c = xf[((cdh * 16 + i + 1) + cs) & 31];
                uint4 pk;
                pk.x = pkh2(a.y, a.x); pk.y = pkh2(a.w, a.z);
                pk.z = pkh2(c.y, c.x); pk.w = pkh2(c.w, c.z);
                *reinterpret_cast<uint4*>(smem + OFF_XH + cs * XH_STRIDE
                                          + (cdh * 8 + (i >> 1)) * 16) = pk;
            }
        }
        __syncthreads();

        if (tile + 1 < NTILE) load_tile(tile + 1, buf ^ 1);

        // ---- GEMM1 (HMMA): scores[32q x 16s] for this warp's slice ----
        float c[2][2][4];
        #pragma unroll
        for (int m = 0; m < 2; ++m)
            #pragma unroll
            for (int n = 0; n < 2; ++n)
                c[m][n][0] = c[m][n][1] = c[m][n][2] = c[m][n][3] = 0.f;

        #pragma unroll
        for (int k = 0; k < 8; ++k) {
            uint32_t bf[2][2];
            #pragma unroll
            for (int n = 0; n < 2; ++n) {
                uint32_t addr = sb + OFF_XH + (wsb + n * 8 + (lane & 7)) * XH_STRIDE
                              + (k * 2 + ((lane >> 3) & 1)) * 16;
                asm volatile("ldmatrix.sync.aligned.m8n8.x2.shared.b16 {%0,%1},[%2];"
                    : "=r"(bf[n][0]), "=r"(bf[n][1]) : "r"(addr));
            }
            #pragma unroll
            for (int m = 0; m < 2; ++m)
                #pragma unroll
                for (int n = 0; n < 2; ++n)
                    asm volatile(
                        "mma.sync.aligned.m16n8k16.row.col.f32.f16.f16.f32 "
                        "{%0,%1,%2,%3},{%4,%5,%6,%7},{%8,%9},{%0,%1,%2,%3};"
                        : "+f"(c[m][n][0]), "+f"(c[m][n][1]),
                          "+f"(c[m][n][2]), "+f"(c[m][n][3])
                        : "r"(qa[m][k][0]), "r"(qa[m][k][1]),
                          "r"(qa[m][k][2]), "r"(qa[m][k][3]),
                          "r"(bf[n][0]), "r"(bf[n][1]));
        }

        // ---- epilogue: mask + exp -> p_sm, lsum in regs ----
        {
            const int scol = (lane & 3) * 2;
            int mk[2][2];
            #pragma unroll
            for (int n = 0; n < 2; ++n) {
                int sg = tile * TS + wsb + n * 8 + scol;
                int2 mv = *reinterpret_cast<const int2*>(m_sm + sg);
                mk[n][0] = mv.x; mk[n][1] = mv.y;
            }
            #pragma unroll
            for (int m = 0; m < 2; ++m)
                #pragma unroll
                for (int h = 0; h < 2; ++h) {
                    int q = m * 16 + h * 8 + (lane >> 2);
                    if (q < kNQ) {
                        float la = 0.f;
                        #pragma unroll
                        for (int n = 0; n < 2; ++n) {
                            float e0 = mk[n][0] ? __expf(c[m][n][h * 2 + 0]) : 0.f;
                            float e1 = mk[n][1] ? __expf(c[m][n][h * 2 + 1]) : 0.f;
                            la += e0 + e1;
                            *reinterpret_cast<float2*>(
                                p_sm + q * P_STRIDE + wsb + n * 8 + scol) =
                                make_float2(e0, e1);
                        }
                        lsum[m * 2 + h] += la;
                    }
                }
        }
        __syncwarp();

        // ---- phase B (SIMT f32x2): acc[q][4d] += p[q][s] * x[s][4d] ----
        {
            const ulonglong2* xt = reinterpret_cast<const ulonglong2*>(xb4 + buf * XBUF_F4);
            const float4* p4 = reinterpret_cast<const float4*>(p_sm);
            #pragma unroll
            for (int i = 0; i < 4; ++i) {
                const int s0 = wsb + i * 4;
                ulonglong2 xq[4];
                #pragma unroll
                for (int k2 = 0; k2 < 4; ++k2)
                    xq[k2] = xt[(s0 + k2) * 32 + ((lane + s0 + k2) & 31)];
                #pragma unroll
                for (int j = 0; j < kNQ; ++j) {
                    float4 pv = p4[j * (P_STRIDE / 4) + (wsb >> 2) + i];
                    unsigned long long p0 = pk2(pv.x, pv.x), p1 = pk2(pv.y, pv.y);
                    unsigned long long p2 = pk2(pv.z, pv.z), p3 = pk2(pv.w, pv.w);
                    acc[j][0] = f2ma(xq[0].x, p0, acc[j][0]);
                    acc[j][1] = f2ma(xq[0].y, p0, acc[j][1]);
                    acc[j][0] = f2ma(xq[1].x, p1, acc[j][0]);
                    acc[j][1] = f2ma(xq[1].y, p1, acc[j][1]);
                    acc[j][0] = f2ma(xq[2].x, p2, acc[j][0]);
                    acc[j][1] = f2ma(xq[2].y, p2, acc[j][1]);
                    acc[j][0] = f2ma(xq[3].x, p3, acc[j][0]);
                    acc[j][1] = f2ma(xq[3].y, p3, acc[j][1]);
                }
            }
        }
    }

    // ---- reduce lsum across lane-quads, stash per-warp ----
    #pragma unroll
    for (int o = 1; o < 4; o <<= 1) {
        #pragma unroll
        for (int v = 0; v < 4; ++v)
            lsum[v] += __shfl_xor_sync(0xffffffffu, lsum[v], o);
    }
    if ((lane & 3) == 0) {
        int a = lane >> 2;
        lr[w * 32 + a]      = lsum[0];
        lr[w * 32 + 8 + a]  = lsum[1];
        lr[w * 32 + 16 + a] = lsum[2];
        lr[w * 32 + 24 + a] = lsum[3];
    }
    __syncthreads();
    if (t < kNQ) {
        float s = 0.f;
        #pragma unroll
        for (int r = 0; r < 8; ++r) s += lr[r * 32 + t];
        li[t] = 1.0f / s;
    }

    // ---- reduce acc across 8 warp-slices through smem (reuse x area) ----
    float4* red4 = reinterpret_cast<float4*>(smem);
    #pragma unroll
    for (int j = 0; j < kNQ; ++j) {
        float2 a = up2(acc[j][0]);
        float2 c = up2(acc[j][1]);
        red4[(w * kNQ + j) * 32 + lane] = make_float4(a.x, a.y, c.x, c.y);
    }
    __syncthreads();

    float* red = reinterpret_cast<float*>(smem);
    float* ob = out + (size_t)b * OUT_PER_B;
    for (int o = t; o < OUT_PER_B; o += THREADS) {
        int q = o >> 7;
        float ssum = 0.f;
        #pragma unroll
        for (int r = 0; r < 8; ++r) ssum += red[r * OUT_PER_B + o];
        ob[o] = ssum * li[q];
    }
}

extern "C" void kernel_launch(void* const* d_in, const int* in_sizes, int n_in,
                              void* d_out, int out_size) {
    const float* x    = (const float*)d_in[0];
    const float* qe   = (const float*)d_in[1];
    const int*   ques = (const int*)d_in[2];
    const int*   mask = (const int*)d_in[3];
    float* out = (float*)d_out;

    cudaFuncSetAttribute(AttentionPooling_main,
                         cudaFuncAttributeMaxDynamicSharedMemorySize, SMEM_BYTES);
    AttentionPooling_main<<<kB, THREADS, SMEM_BYTES>>>(x, qe, ques, mask, out);
}

// round 10
// speedup vs baseline: 1.8725x; 1.1903x over previous
#include <cuda_runtime.h>
#include <cuda_fp16.h>
#include <cstdint>

namespace {
constexpr int kB = 128, kS = 2048, kD = 128, kNQ = 18;
constexpr int TS = 128, NTILE = kS / TS, THREADS = 256;
constexpr float SCALE = 0.08838834764831845f;   // 1/sqrt(128)
constexpr int XBUF_F4 = TS * 32;                // float4 per f32 x buffer
constexpr int PITCH = 272;                      // fp16 row pitch (256B + 16 pad)

constexpr int OFF_XH = 131072;                  // x fp16 hi  [128][272]
constexpr int OFF_XL = OFF_XH + TS * PITCH;     // x fp16 lo residual
constexpr int OFF_Q  = OFF_XL + TS * PITCH;     // q fp16 [32][272]
constexpr int OFF_PH = OFF_Q  + 32 * PITCH;     // p fp16 hi [32][272]
constexpr int OFF_PL = OFF_PH + 32 * PITCH;     // p fp16 lo
constexpr int OFF_LR = OFF_PL + 32 * PITCH;     // per-warp row sums (1KB)
constexpr int OFF_LI = OFF_LR + 1024;           // inv sums (128B)
constexpr int OFF_MB = OFF_LI + 128;            // mask bytes (2KB)
constexpr int SMEM_BYTES = OFF_MB + 2048;       // 230016 <= 232448
constexpr int OUT_PER_B = kNQ * kD;
}

__device__ __forceinline__ void cpa16(void* dst, const void* src) {
    unsigned a = (unsigned)__cvta_generic_to_shared(dst);
    asm volatile("cp.async.cg.shared.global [%0], [%1], 16;" :: "r"(a), "l"(src));
}
__device__ __forceinline__ void ldsm_x4(uint32_t* r, uint32_t a) {
    asm volatile("ldmatrix.sync.aligned.m8n8.x4.shared.b16 {%0,%1,%2,%3},[%4];"
        : "=r"(r[0]), "=r"(r[1]), "=r"(r[2]), "=r"(r[3]) : "r"(a));
}
__device__ __forceinline__ void ldsm_x2(uint32_t* r, uint32_t a) {
    asm volatile("ldmatrix.sync.aligned.m8n8.x2.shared.b16 {%0,%1},[%2];"
        : "=r"(r[0]), "=r"(r[1]) : "r"(a));
}
__device__ __forceinline__ void ldsm_x2t(uint32_t* r, uint32_t a) {
    asm volatile("ldmatrix.sync.aligned.m8n8.x2.trans.shared.b16 {%0,%1},[%2];"
        : "=r"(r[0]), "=r"(r[1]) : "r"(a));
}
__device__ __forceinline__ void mma16816(float* c, const uint32_t* a, const uint32_t* b) {
    asm volatile("mma.sync.aligned.m16n8k16.row.col.f32.f16.f16.f32 "
        "{%0,%1,%2,%3},{%4,%5,%6,%7},{%8,%9},{%0,%1,%2,%3};"
        : "+f"(c[0]), "+f"(c[1]), "+f"(c[2]), "+f"(c[3])
        : "r"(a[0]), "r"(a[1]), "r"(a[2]), "r"(a[3]), "r"(b[0]), "r"(b[1]));
}
__device__ __forceinline__ uint32_t h2u(__half2 h) {
    uint32_t u; *reinterpret_cast<__half2*>(&u) = h; return u;
}

__global__ void __launch_bounds__(THREADS, 1)
AttentionPooling_main(const float* __restrict__ x,
                      const float* __restrict__ qe,
                      const int*   __restrict__ ques,
                      const int*   __restrict__ mask,
                      float*       __restrict__ out)
{
    extern __shared__ char smem[];
    float4*  xb4 = reinterpret_cast<float4*>(smem);
    float*   lr  = reinterpret_cast<float*>(smem + OFF_LR);
    float*   li  = reinterpret_cast<float*>(smem + OFF_LI);
    uint8_t* m8  = reinterpret_cast<uint8_t*>(smem + OFF_MB);

    const int t = threadIdx.x, w = t >> 5, lane = t & 31;
    const int b = blockIdx.x;
    const int wsb = w * 16;                       // phase A s-slice / p col base
    const int wnb = w * 16;                       // phase B d-slice base
    const int g = lane >> 2, scol = (lane & 3) * 2;
    const uint32_t sb = (uint32_t)__cvta_generic_to_shared(smem);

    // ---- x tile 0 async ----
    const float* xb = x + (size_t)b * kS * kD;
    auto load_tile = [&](int tile, int buf) {
        const float* src = xb + tile * TS * kD;
        float4* dst = xb4 + buf * XBUF_F4;
        #pragma unroll
        for (int k = 0; k < 16; ++k) {
            int i = t + k * THREADS;
            int s = i >> 5, d4 = i & 31;
            cpa16(&dst[s * 32 + ((d4 + s) & 31)], src + s * kD + d4 * 4);
        }
        asm volatile("cp.async.commit_group;");
    };
    load_tile(0, 0);

    // ---- mask -> bytes in smem ----
    for (int i = t; i < kS / 4; i += THREADS) {
        int4 mv = reinterpret_cast<const int4*>(mask + b * kS)[i];
        uint32_t pk = (mv.x & 1) | ((mv.y & 1) << 8) |
                      ((mv.z & 1) << 16) | ((mv.w & 1) << 24);
        *reinterpret_cast<uint32_t*>(m8 + i * 4) = pk;
    }

    // ---- q gather: fp16 [32 rows][272B], rows >= kNQ zeroed ----
    for (int i = t; i < 32 * 16; i += THREADS) {
        int j = i >> 4, c = i & 15;
        uint4 pk = make_uint4(0u, 0u, 0u, 0u);
        if (j < kNQ) {
            int qi = ques[b * kNQ + j];
            const float4* qr = reinterpret_cast<const float4*>(qe + qi * kD);
            float4 v0 = qr[c * 2], v1 = qr[c * 2 + 1];
            pk.x = h2u(__floats2half2_rn(v0.x * SCALE, v0.y * SCALE));
            pk.y = h2u(__floats2half2_rn(v0.z * SCALE, v0.w * SCALE));
            pk.z = h2u(__floats2half2_rn(v1.x * SCALE, v1.y * SCALE));
            pk.w = h2u(__floats2half2_rn(v1.z * SCALE, v1.w * SCALE));
        }
        *reinterpret_cast<uint4*>(smem + OFF_Q + j * PITCH + c * 16) = pk;
    }
    // ---- zero PH/PL rows 18..31 (never written again) ----
    for (int i = t; i < 14 * 17; i += THREADS) {
        int r = i / 17, c = i % 17;
        uint4 z = make_uint4(0u, 0u, 0u, 0u);
        *reinterpret_cast<uint4*>(smem + OFF_PH + (18 + r) * PITCH + c * 16) = z;
        *reinterpret_cast<uint4*>(smem + OFF_PL + (18 + r) * PITCH + c * 16) = z;
    }
    __syncthreads();

    // ---- hoist q A-fragments (proven R9 pattern) ----
    uint32_t qa[2][8][4];
    #pragma unroll
    for (int m = 0; m < 2; ++m)
        #pragma unroll
        for (int k = 0; k < 8; ++k)
            ldsm_x4(qa[m][k], sb + OFF_Q + (m * 16 + (lane & 15)) * PITCH
                              + (k * 2 + (lane >> 4)) * 16);

    // persistent output accumulators: q(32) x d(16-slice)
    float co[2][2][4];
    #pragma unroll
    for (int m = 0; m < 2; ++m)
        #pragma unroll
        for (int n = 0; n < 2; ++n)
            co[m][n][0] = co[m][n][1] = co[m][n][2] = co[m][n][3] = 0.f;
    float lsum[4] = {0.f, 0.f, 0.f, 0.f};

    const int cs = t & 127, cdh = t >> 7;          // convert: row, d-half

    for (int tile = 0; tile < NTILE; ++tile) {
        const int buf = tile & 1;
        asm volatile("cp.async.wait_group 0;" ::: "memory");
        __syncthreads();
        if (tile + 1 < NTILE) load_tile(tile + 1, buf ^ 1);

        // ---- convert x f32 -> fp16 hi + lo residual ----
        {
            const float4* xf = xb4 + buf * XBUF_F4 + (size_t)cs * 32;
            char* rowH = smem + OFF_XH + cs * PITCH + cdh * 128;
            char* rowL = smem + OFF_XL + cs * PITCH + cdh * 128;
            #pragma unroll
            for (int i = 0; i < 16; i += 2) {
                float4 a = xf[((cdh * 16 + i)     + cs) & 31];
                float4 c = xf[((cdh * 16 + i + 1) + cs) & 31];
                __half2 h0 = __floats2half2_rn(a.x, a.y), h1 = __floats2half2_rn(a.z, a.w);
                __half2 h2 = __floats2half2_rn(c.x, c.y), h3 = __floats2half2_rn(c.z, c.w);
                uint4 ph = make_uint4(h2u(h0), h2u(h1), h2u(h2), h2u(h3));
                uint4 pl = make_uint4(
                    h2u(__floats2half2_rn(a.x - __low2float(h0), a.y - __high2float(h0))),
                    h2u(__floats2half2_rn(a.z - __low2float(h1), a.w - __high2float(h1))),
                    h2u(__floats2half2_rn(c.x - __low2float(h2), c.y - __high2float(h2))),
                    h2u(__floats2half2_rn(c.z - __low2float(h3), c.w - __high2float(h3))));
                *reinterpret_cast<uint4*>(rowH + (i >> 1) * 16) = ph;
                *reinterpret_cast<uint4*>(rowL + (i >> 1) * 16) = pl;
            }
        }
        __syncthreads();

        // ---- phase A (HMMA): scores[32q x 16s own slice] from XH ----
        float c[2][2][4];
        #pragma unroll
        for (int m = 0; m < 2; ++m)
            #pragma unroll
            for (int n = 0; n < 2; ++n)
                c[m][n][0] = c[m][n][1] = c[m][n][2] = c[m][n][3] = 0.f;
        #pragma unroll
        for (int k = 0; k < 8; ++k) {
            uint32_t bf[2][2];
            #pragma unroll
            for (int n = 0; n < 2; ++n)
                ldsm_x2(bf[n], sb + OFF_XH + (wsb + n * 8 + (lane & 7)) * PITCH
                               + (k * 2 + ((lane >> 3) & 1)) * 16);
            #pragma unroll
            for (int m = 0; m < 2; ++m)
                #pragma unroll
                for (int n = 0; n < 2; ++n)
                    mma16816(c[m][n], qa[m][k], bf[n]);
        }

        // ---- epilogue: mask+exp, p -> fp16 hi/lo smem, lsum in regs ----
        {
            uchar2 mv[2];
            #pragma unroll
            for (int n = 0; n < 2; ++n)
                mv[n] = *reinterpret_cast<const uchar2*>(
                    m8 + tile * TS + wsb + n * 8 + scol);
            #pragma unroll
            for (int m = 0; m < 2; ++m)
                #pragma unroll
                for (int h = 0; h < 2; ++h) {
                    int q = m * 16 + h * 8 + g;
                    if (q < kNQ) {
                        float la = 0.f;
                        #pragma unroll
                        for (int n = 0; n < 2; ++n) {
                            float e0 = mv[n].x ? __expf(c[m][n][h * 2 + 0]) : 0.f;
                            float e1 = mv[n].y ? __expf(c[m][n][h * 2 + 1]) : 0.f;
                            la += e0 + e1;
                            __half2 ph = __floats2half2_rn(e0, e1);
                            __half2 pl = __floats2half2_rn(e0 - __low2float(ph),
                                                           e1 - __high2float(ph));
                            int off = q * PITCH + (wsb + n * 8 + scol) * 2;
                            *reinterpret_cast<uint32_t*>(smem + OFF_PH + off) = h2u(ph);
                            *reinterpret_cast<uint32_t*>(smem + OFF_PL + off) = h2u(pl);
                        }
                        lsum[m * 2 + h] += la;
                    }
                }
        }
        __syncthreads();

        // ---- phase B (HMMA): co += p(hi+lo) . x(hi+lo), 3 passes ----
        #pragma unroll
        for (int k = 0; k < 8; ++k) {
            uint32_t ah[2][4], al[2][4];
            #pragma unroll
            for (int m = 0; m < 2; ++m) {
                uint32_t off = (m * 16 + (lane & 15)) * PITCH + k * 32 + (lane >> 4) * 16;
                ldsm_x4(ah[m], sb + OFF_PH + off);
                ldsm_x4(al[m], sb + OFF_PL + off);
            }
            uint32_t bh[2][2], bl[2][2];
            #pragma unroll
            for (int n = 0; n < 2; ++n) {
                uint32_t off = (k * 16 + (lane & 7) + ((lane >> 3) & 1) * 8) * PITCH
                             + (wnb + n * 8) * 2;
                ldsm_x2t(bh[n], sb + OFF_XH + off);
                ldsm_x2t(bl[n], sb + OFF_XL + off);
            }
            #pragma unroll
            for (int m = 0; m < 2; ++m)
                #pragma unroll
                for (int n = 0; n < 2; ++n) {
                    mma16816(co[m][n], ah[m], bh[n]);
                    mma16816(co[m][n], ah[m], bl[n]);
                    mma16816(co[m][n], al[m], bh[n]);
                }
        }
    }

    // ---- reduce lsum across lane-quads, per-warp stash, invert ----
    #pragma unroll
    for (int o = 1; o < 4; o <<= 1)
        #pragma unroll
        for (int v = 0; v < 4; ++v)
            lsum[v] += __shfl_xor_sync(0xffffffffu, lsum[v], o);
    if ((lane & 3) == 0) {
        lr[w * 32 + g]      = lsum[0];
        lr[w * 32 + 8 + g]  = lsum[1];
        lr[w * 32 + 16 + g] = lsum[2];
        lr[w * 32 + 24 + g] = lsum[3];
    }
    __syncthreads();
    if (t < kNQ) {
        float s = 0.f;
        #pragma unroll
        for (int r = 0; r < 8; ++r) s += lr[r * 32 + t];
        li[t] = 1.0f / s;
    }
    __syncthreads();

    // ---- store output directly from C-fragments ----
    float* ob = out + (size_t)b * OUT_PER_B;
    #pragma unroll
    for (int m = 0; m < 2; ++m)
        #pragma unroll
        for (int h = 0; h < 2; ++h) {
            int q = m * 16 + h * 8 + g;
            if (q < kNQ) {
                float inv = li[q];
                #pragma unroll
                for (int n = 0; n < 2; ++n) {
                    int d = wnb + n * 8 + scol;
                    *reinterpret_cast<float2*>(ob + q * kD + d) =
                        make_float2(co[m][n][h * 2] * inv, co[m][n][h * 2 + 1] * inv);
                }
            }
        }
}

extern "C" void kernel_launch(void* const* d_in, const int* in_sizes, int n_in,
                              void* d_out, int out_size) {
    const float* x    = (const float*)d_in[0];
    const float* qe   = (const float*)d_in[1];
    const int*   ques = (const int*)d_in[2];
    const int*   mask = (const int*)d_in[3];
    float* out = (float*)d_out;

    cudaFuncSetAttribute(AttentionPooling_main,
                         cudaFuncAttributeMaxDynamicSharedMemorySize, SMEM_BYTES);
    AttentionPooling_main<<<kB, THREADS, SMEM_BYTES>>>(x, qe, ques, mask, out);
}

// round 12
// speedup vs baseline: 2.2028x; 1.1764x over previous
#include <cuda_runtime.h>
#include <cuda_fp16.h>
#include <cstdint>

namespace {
constexpr int kB = 128, kS = 2048, kD = 128, kNQ = 18;
constexpr int TS = 128, NTILE = kS / TS, THREADS = 256;
constexpr float SCALE = 0.08838834764831845f;   // 1/sqrt(128)
constexpr int PITCH = 272;                      // fp16 row pitch (256B + 16 pad)

constexpr int OFF_XH = 0;                       // x fp16 hi  [128][272]
constexpr int OFF_XL = OFF_XH + TS * PITCH;     // x fp16 lo residual
constexpr int OFF_Q  = OFF_XL + TS * PITCH;     // q fp16 [32][272]
constexpr int OFF_PH = OFF_Q  + 32 * PITCH;     // p fp16 hi [32][272]
constexpr int OFF_PL = OFF_PH + 32 * PITCH;     // p fp16 lo
constexpr int OFF_LR = OFF_PL + 32 * PITCH;     // per-warp row sums (1KB)
constexpr int OFF_LI = OFF_LR + 1024;           // inv sums (128B)
constexpr int OFF_MB = OFF_LI + 128;            // mask bytes (2KB)
constexpr int SMEM_BYTES = OFF_MB + 2048;       // 98944 B
constexpr int OUT_PER_B = kNQ * kD;
}

__device__ __forceinline__ void ldsm_x4(uint32_t* r, uint32_t a) {
    asm volatile("ldmatrix.sync.aligned.m8n8.x4.shared.b16 {%0,%1,%2,%3},[%4];"
        : "=r"(r[0]), "=r"(r[1]), "=r"(r[2]), "=r"(r[3]) : "r"(a));
}
__device__ __forceinline__ void ldsm_x2(uint32_t* r, uint32_t a) {
    asm volatile("ldmatrix.sync.aligned.m8n8.x2.shared.b16 {%0,%1},[%2];"
        : "=r"(r[0]), "=r"(r[1]) : "r"(a));
}
__device__ __forceinline__ void ldsm_x2t(uint32_t* r, uint32_t a) {
    asm volatile("ldmatrix.sync.aligned.m8n8.x2.trans.shared.b16 {%0,%1},[%2];"
        : "=r"(r[0]), "=r"(r[1]) : "r"(a));
}
__device__ __forceinline__ void mma16816(float* c, const uint32_t* a, const uint32_t* b) {
    asm volatile("mma.sync.aligned.m16n8k16.row.col.f32.f16.f16.f32 "
        "{%0,%1,%2,%3},{%4,%5,%6,%7},{%8,%9},{%0,%1,%2,%3};"
        : "+f"(c[0]), "+f"(c[1]), "+f"(c[2]), "+f"(c[3])
        : "r"(a[0]), "r"(a[1]), "r"(a[2]), "r"(a[3]), "r"(b[0]), "r"(b[1]));
}
__device__ __forceinline__ uint32_t h2u(__half2 h) {
    uint32_t u; *reinterpret_cast<__half2*>(&u) = h; return u;
}

__global__ void __launch_bounds__(THREADS, 1)
AttentionPooling_main(const float* __restrict__ x,
                      const float* __restrict__ qe,
                      const int*   __restrict__ ques,
                      const int*   __restrict__ mask,
                      float*       __restrict__ out)
{
    extern __shared__ char smem[];
    float*   lr = reinterpret_cast<float*>(smem + OFF_LR);
    float*   li = reinterpret_cast<float*>(smem + OFF_LI);
    uint8_t* m8 = reinterpret_cast<uint8_t*>(smem + OFF_MB);

    const int t = threadIdx.x, w = t >> 5, lane = t & 31;
    const int b = blockIdx.x;
    const int wsb = w * 16;                       // phase A s-slice / phase B d-slice
    const int g = lane >> 2, scol = (lane & 3) * 2;
    const uint32_t sb = (uint32_t)__cvta_generic_to_shared(smem);

    const float4* xb4 = reinterpret_cast<const float4*>(x + (size_t)b * kS * kD);

    // ---- prefetch FULL x tile 0 into registers (16 x LDG.128, coalesced) ----
    float4 xpre[16];
    #pragma unroll
    for (int i = 0; i < 16; ++i) xpre[i] = xb4[t + i * THREADS];

    // ---- mask -> bytes in smem ----
    for (int i = t; i < kS / 4; i += THREADS) {
        int4 mv = reinterpret_cast<const int4*>(mask + b * kS)[i];
        uint32_t pk = (mv.x & 1) | ((mv.y & 1) << 8) |
                      ((mv.z & 1) << 16) | ((mv.w & 1) << 24);
        *reinterpret_cast<uint32_t*>(m8 + i * 4) = pk;
    }

    // ---- q gather: fp16 [32 rows][272B], rows >= kNQ zeroed ----
    for (int i = t; i < 32 * 16; i += THREADS) {
        int j = i >> 4, c = i & 15;
        uint4 pk = make_uint4(0u, 0u, 0u, 0u);
        if (j < kNQ) {
            int qi = ques[b * kNQ + j];
            const float4* qr = reinterpret_cast<const float4*>(qe + qi * kD);
            float4 v0 = qr[c * 2], v1 = qr[c * 2 + 1];
            pk.x = h2u(__floats2half2_rn(v0.x * SCALE, v0.y * SCALE));
            pk.y = h2u(__floats2half2_rn(v0.z * SCALE, v0.w * SCALE));
            pk.z = h2u(__floats2half2_rn(v1.x * SCALE, v1.y * SCALE));
            pk.w = h2u(__floats2half2_rn(v1.z * SCALE, v1.w * SCALE));
        }
        *reinterpret_cast<uint4*>(smem + OFF_Q + j * PITCH + c * 16) = pk;
    }
    // ---- zero PH/PL rows 18..31 (never written again) ----
    for (int i = t; i < 14 * 17; i += THREADS) {
        int r = i / 17, c = i % 17;
        uint4 z = make_uint4(0u, 0u, 0u, 0u);
        *reinterpret_cast<uint4*>(smem + OFF_PH + (18 + r) * PITCH + c * 16) = z;
        *reinterpret_cast<uint4*>(smem + OFF_PL + (18 + r) * PITCH + c * 16) = z;
    }
    __syncthreads();

    // ---- hoist q A-fragments (proven pattern) ----
    uint32_t qa[2][8][4];
    #pragma unroll
    for (int m = 0; m < 2; ++m)
        #pragma unroll
        for (int k = 0; k < 8; ++k)
            ldsm_x4(qa[m][k], sb + OFF_Q + (m * 16 + (lane & 15)) * PITCH
                              + (k * 2 + (lane >> 4)) * 16);

    // persistent output accumulators: q(32) x d(16-slice)
    float co[2][2][4];
    #pragma unroll
    for (int m = 0; m < 2; ++m)
        #pragma unroll
        for (int n = 0; n < 2; ++n)
            co[m][n][0] = co[m][n][1] = co[m][n][2] = co[m][n][3] = 0.f;
    float lsum[4] = {0.f, 0.f, 0.f, 0.f};

    for (int tile = 0; tile < NTILE; ++tile) {
        // ---- convert x (regs) -> fp16 hi + lo residual in smem ----
        // chunk i: idx = t + i*256 -> row s = w + i*8, col float4 = lane
        {
            #pragma unroll
            for (int i = 0; i < 16; ++i) {
                float4 a = xpre[i];
                int s = w + i * 8;
                __half2 h0 = __floats2half2_rn(a.x, a.y);
                __half2 h1 = __floats2half2_rn(a.z, a.w);
                uint2 ph = make_uint2(h2u(h0), h2u(h1));
                uint2 pl = make_uint2(
                    h2u(__floats2half2_rn(a.x - __low2float(h0), a.y - __high2float(h0))),
                    h2u(__floats2half2_rn(a.z - __low2float(h1), a.w - __high2float(h1))));
                *reinterpret_cast<uint2*>(smem + OFF_XH + s * PITCH + lane * 8) = ph;
                *reinterpret_cast<uint2*>(smem + OFF_XL + s * PITCH + lane * 8) = pl;
            }
        }
        __syncthreads();

        // ---- prefetch next tile into registers (hidden by A + B) ----
        if (tile + 1 < NTILE) {
            const float4* src = xb4 + (tile + 1) * (TS * 32);
            #pragma unroll
            for (int i = 0; i < 16; ++i) xpre[i] = src[t + i * THREADS];
        }

        // ---- phase A (HMMA): scores[32q x 16s own slice] from XH ----
        float c[2][2][4];
        #pragma unroll
        for (int m = 0; m < 2; ++m)
            #pragma unroll
            for (int n = 0; n < 2; ++n)
                c[m][n][0] = c[m][n][1] = c[m][n][2] = c[m][n][3] = 0.f;
        #pragma unroll
        for (int k = 0; k < 8; ++k) {
            uint32_t bf[2][2];
            #pragma unroll
            for (int n = 0; n < 2; ++n)
                ldsm_x2(bf[n], sb + OFF_XH + (wsb + n * 8 + (lane & 7)) * PITCH
                               + (k * 2 + ((lane >> 3) & 1)) * 16);
            #pragma unroll
            for (int m = 0; m < 2; ++m)
                #pragma unroll
                for (int n = 0; n < 2; ++n)
                    mma16816(c[m][n], qa[m][k], bf[n]);
        }

        // ---- epilogue: mask+exp, p -> fp16 hi/lo smem, lsum in regs ----
        {
            uchar2 mv[2];
            #pragma unroll
            for (int n = 0; n < 2; ++n)
                mv[n] = *reinterpret_cast<const uchar2*>(
                    m8 + tile * TS + wsb + n * 8 + scol);
            #pragma unroll
            for (int m = 0; m < 2; ++m)
                #pragma unroll
                for (int h = 0; h < 2; ++h) {
                    int q = m * 16 + h * 8 + g;
                    if (q < kNQ) {
                        float la = 0.f;
                        #pragma unroll
                        for (int n = 0; n < 2; ++n) {
                            float e0 = mv[n].x ? __expf(c[m][n][h * 2 + 0]) : 0.f;
                            float e1 = mv[n].y ? __expf(c[m][n][h * 2 + 1]) : 0.f;
                            la += e0 + e1;
                            __half2 ph = __floats2half2_rn(e0, e1);
                            __half2 pl = __floats2half2_rn(e0 - __low2float(ph),
                                                           e1 - __high2float(ph));
                            int off = q * PITCH + (wsb + n * 8 + scol) * 2;
                            *reinterpret_cast<uint32_t*>(smem + OFF_PH + off) = h2u(ph);
                            *reinterpret_cast<uint32_t*>(smem + OFF_PL + off) = h2u(pl);
                        }
                        lsum[m * 2 + h] += la;
                    }
                }
        }
        __syncthreads();

        // ---- phase B (HMMA): co += p(hi+lo) . x(hi+lo), 3 passes ----
        #pragma unroll
        for (int k = 0; k < 8; ++k) {
            uint32_t ah[2][4], al[2][4];
            #pragma unroll
            for (int m = 0; m < 2; ++m) {
                uint32_t off = (m * 16 + (lane & 15)) * PITCH + k * 32 + (lane >> 4) * 16;
                ldsm_x4(ah[m], sb + OFF_PH + off);
                ldsm_x4(al[m], sb + OFF_PL + off);
            }
            uint32_t bh[2][2], bl[2][2];
            #pragma unroll
            for (int n = 0; n < 2; ++n) {
                uint32_t off = (k * 16 + (lane & 7) + ((lane >> 3) & 1) * 8) * PITCH
                             + (wsb + n * 8) * 2;
                ldsm_x2t(bh[n], sb + OFF_XH + off);
                ldsm_x2t(bl[n], sb + OFF_XL + off);
            }
            #pragma unroll
            for (int m = 0; m < 2; ++m)
                #pragma unroll
                for (int n = 0; n < 2; ++n) {
                    mma16816(co[m][n], ah[m], bh[n]);
                    mma16816(co[m][n], ah[m], bl[n]);
                    mma16816(co[m][n], al[m], bh[n]);
                }
        }
        __syncthreads();    // WAR: next convert overwrites XH/XL
    }

    // ---- reduce lsum across lane-quads, per-warp stash, invert ----
    #pragma unroll
    for (int o = 1; o < 4; o <<= 1)
        #pragma unroll
        for (int v = 0; v < 4; ++v)
            lsum[v] += __shfl_xor_sync(0xffffffffu, lsum[v], o);
    if ((lane & 3) == 0) {
        lr[w * 32 + g]      = lsum[0];
        lr[w * 32 + 8 + g]  = lsum[1];
        lr[w * 32 + 16 + g] = lsum[2];
        lr[w * 32 + 24 + g] = lsum[3];
    }
    __syncthreads();
    if (t < kNQ) {
        float s = 0.f;
        #pragma unroll
        for (int r = 0; r < 8; ++r) s += lr[r * 32 + t];
        li[t] = 1.0f / s;
    }
    __syncthreads();

    // ---- store output directly from C-fragments ----
    float* ob = out + (size_t)b * OUT_PER_B;
    #pragma unroll
    for (int m = 0; m < 2; ++m)
        #pragma unroll
        for (int h = 0; h < 2; ++h) {
            int q = m * 16 + h * 8 + g;
            if (q < kNQ) {
                float inv = li[q];
                #pragma unroll
                for (int n = 0; n < 2; ++n) {
                    int d = wsb + n * 8 + scol;
                    *reinterpret_cast<float2*>(ob + q * kD + d) =
                        make_float2(co[m][n][h * 2] * inv, co[m][n][h * 2 + 1] * inv);
                }
            }
        }
}

extern "C" void kernel_launch(void* const* d_in, const int* in_sizes, int n_in,
                              void* d_out, int out_size) {
    const float* x    = (const float*)d_in[0];
    const float* qe   = (const float*)d_in[1];
    const int*   ques = (const int*)d_in[2];
    const int*   mask = (const int*)d_in[3];
    float* out = (float*)d_out;

    cudaFuncSetAttribute(AttentionPooling_main,
                         cudaFuncAttributeMaxDynamicSharedMemorySize, SMEM_BYTES);
    AttentionPooling_main<<<kB, THREADS, SMEM_BYTES>>>(x, qe, ques, mask, out);
}

// round 13
// speedup vs baseline: 2.6207x; 1.1897x over previous
#include <cuda_runtime.h>
#include <cuda_fp16.h>
#include <cstdint>

namespace {
constexpr int kB = 128, kS = 2048, kD = 128, kNQ = 18;
constexpr int TS = 128, NTILE = kS / TS, THREADS = 256;
constexpr float SCALE = 0.08838834764831845f;   // 1/sqrt(128)
constexpr int PITCH = 272;                      // fp16 row pitch (256B + 16 pad)
constexpr int XBUF  = TS * PITCH;               // 34816 B per XH buffer
constexpr int PBUF  = 32 * PITCH;               // 8704 B per PH buffer

constexpr int OFF_XH = 0;                       // x fp16 [3 buffers][128][272]
constexpr int OFF_Q  = OFF_XH + 3 * XBUF;       // 104448: q fp16 [32][272]
constexpr int OFF_PH = OFF_Q + PBUF;            // 113152: p fp16 [2 buffers][32][272]
constexpr int OFF_LR = OFF_PH + 2 * PBUF;       // 130560: per-warp row sums
constexpr int OFF_LI = OFF_LR + 1024;           // 131584: inv sums
constexpr int OFF_MB = OFF_LI + 128;            // 131712: mask bytes
constexpr int SMEM_BYTES = OFF_MB + 2048;       // 133760 <= 232448
constexpr int OUT_PER_B = kNQ * kD;
}

__device__ __forceinline__ void ldsm_x4(uint32_t* r, uint32_t a) {
    asm volatile("ldmatrix.sync.aligned.m8n8.x4.shared.b16 {%0,%1,%2,%3},[%4];"
        : "=r"(r[0]), "=r"(r[1]), "=r"(r[2]), "=r"(r[3]) : "r"(a));
}
__device__ __forceinline__ void ldsm_x2(uint32_t* r, uint32_t a) {
    asm volatile("ldmatrix.sync.aligned.m8n8.x2.shared.b16 {%0,%1},[%2];"
        : "=r"(r[0]), "=r"(r[1]) : "r"(a));
}
__device__ __forceinline__ void ldsm_x2t(uint32_t* r, uint32_t a) {
    asm volatile("ldmatrix.sync.aligned.m8n8.x2.trans.shared.b16 {%0,%1},[%2];"
        : "=r"(r[0]), "=r"(r[1]) : "r"(a));
}
__device__ __forceinline__ void mma16816(float* c, const uint32_t* a, const uint32_t* b) {
    asm volatile("mma.sync.aligned.m16n8k16.row.col.f32.f16.f16.f32 "
        "{%0,%1,%2,%3},{%4,%5,%6,%7},{%8,%9},{%0,%1,%2,%3};"
        : "+f"(c[0]), "+f"(c[1]), "+f"(c[2]), "+f"(c[3])
        : "r"(a[0]), "r"(a[1]), "r"(a[2]), "r"(a[3]), "r"(b[0]), "r"(b[1]));
}
__device__ __forceinline__ uint32_t h2u(__half2 h) {
    uint32_t u; *reinterpret_cast<__half2*>(&u) = h; return u;
}

__global__ void __launch_bounds__(THREADS, 1)
AttentionPooling_main(const float* __restrict__ x,
                      const float* __restrict__ qe,
                      const int*   __restrict__ ques,
                      const int*   __restrict__ mask,
                      float*       __restrict__ out)
{
    extern __shared__ char smem[];
    float*   lr = reinterpret_cast<float*>(smem + OFF_LR);
    float*   li = reinterpret_cast<float*>(smem + OFF_LI);
    uint8_t* m8 = reinterpret_cast<uint8_t*>(smem + OFF_MB);

    const int t = threadIdx.x, w = t >> 5, lane = t & 31;
    const int b = blockIdx.x;
    const int wsb = w * 16;                     // phase A s-slice / phase B d-slice
    const int g = lane >> 2, scol = (lane & 3) * 2;
    const uint32_t sb = (uint32_t)__cvta_generic_to_shared(smem);

    const float4* xb4 = reinterpret_cast<const float4*>(x + (size_t)b * kS * kD);

    // ---- prefetch FULL x tile 0 into registers ----
    float4 xpre[16];
    #pragma unroll
    for (int i = 0; i < 16; ++i) xpre[i] = xb4[t + i * THREADS];

    // ---- mask -> bytes in smem ----
    for (int i = t; i < kS / 4; i += THREADS) {
        int4 mv = reinterpret_cast<const int4*>(mask + b * kS)[i];
        uint32_t pk = (mv.x & 1) | ((mv.y & 1) << 8) |
                      ((mv.z & 1) << 16) | ((mv.w & 1) << 24);
        *reinterpret_cast<uint32_t*>(m8 + i * 4) = pk;
    }

    // ---- q gather: fp16 [32 rows][272B], rows >= kNQ zeroed ----
    for (int i = t; i < 32 * 16; i += THREADS) {
        int j = i >> 4, c = i & 15;
        uint4 pk = make_uint4(0u, 0u, 0u, 0u);
        if (j < kNQ) {
            int qi = ques[b * kNQ + j];
            const float4* qr = reinterpret_cast<const float4*>(qe + qi * kD);
            float4 v0 = qr[c * 2], v1 = qr[c * 2 + 1];
            pk.x = h2u(__floats2half2_rn(v0.x * SCALE, v0.y * SCALE));
            pk.y = h2u(__floats2half2_rn(v0.z * SCALE, v0.w * SCALE));
            pk.z = h2u(__floats2half2_rn(v1.x * SCALE, v1.y * SCALE));
            pk.w = h2u(__floats2half2_rn(v1.z * SCALE, v1.w * SCALE));
        }
        *reinterpret_cast<uint4*>(smem + OFF_Q + j * PITCH + c * 16) = pk;
    }
    // ---- zero PH rows 18..31 in BOTH buffers (never written again) ----
    for (int i = t; i < 2 * 14 * 17; i += THREADS) {
        int bb = i / (14 * 17), r = (i / 17) % 14, c = i % 17;
        *reinterpret_cast<uint4*>(smem + OFF_PH + bb * PBUF + (18 + r) * PITCH + c * 16)
            = make_uint4(0u, 0u, 0u, 0u);
    }
    __syncthreads();

    // ---- hoist q A-fragments ----
    uint32_t qa[2][8][4];
    #pragma unroll
    for (int m = 0; m < 2; ++m)
        #pragma unroll
        for (int k = 0; k < 8; ++k)
            ldsm_x4(qa[m][k], sb + OFF_Q + (m * 16 + (lane & 15)) * PITCH
                              + (k * 2 + (lane >> 4)) * 16);

    // persistent output accumulators + row sums
    float co[2][2][4];
    #pragma unroll
    for (int m = 0; m < 2; ++m)
        #pragma unroll
        for (int n = 0; n < 2; ++n)
            co[m][n][0] = co[m][n][1] = co[m][n][2] = co[m][n][3] = 0.f;
    float lsum[4] = {0.f, 0.f, 0.f, 0.f};

    // ---- helpers ----
    auto convert = [&](int xbase) {       // xpre -> fp16 into XH buffer
        #pragma unroll
        for (int i = 0; i < 16; ++i) {
            float4 a = xpre[i];
            int s = w + i * 8;
            uint2 ph = make_uint2(h2u(__floats2half2_rn(a.x, a.y)),
                                  h2u(__floats2half2_rn(a.z, a.w)));
            *reinterpret_cast<uint2*>(smem + xbase + s * PITCH + lane * 8) = ph;
        }
    };
    auto phaseB = [&](int xbase, int pbase) {
        #pragma unroll
        for (int k = 0; k < 8; ++k) {
            uint32_t ah[2][4];
            #pragma unroll
            for (int m = 0; m < 2; ++m)
                ldsm_x4(ah[m], sb + pbase + (m * 16 + (lane & 15)) * PITCH
                               + k * 32 + (lane >> 4) * 16);
            uint32_t bh[2][2];
            #pragma unroll
            for (int n = 0; n < 2; ++n)
                ldsm_x2t(bh[n], sb + xbase + (k * 16 + (lane & 7)
                               + ((lane >> 3) & 1) * 8) * PITCH + (wsb + n * 8) * 2);
            #pragma unroll
            for (int m = 0; m < 2; ++m)
                #pragma unroll
                for (int n = 0; n < 2; ++n)
                    mma16816(co[m][n], ah[m], bh[n]);
        }
    };

    // ---- prologue: convert tile0 -> buf0, prefetch tile1 ----
    convert(OFF_XH);
    {
        const float4* src = xb4 + 1 * (TS * 32);
        #pragma unroll
        for (int i = 0; i < 16; ++i) xpre[i] = src[t + i * THREADS];
    }
    __syncthreads();

    int bprev = 2, bcur = 0, bnxt = 1;
    for (int tile = 0; tile < NTILE; ++tile) {
        // ---- phase B for previous tile (reads XH[bprev], PH[(tile-1)&1]) ----
        if (tile > 0)
            phaseB(OFF_XH + bprev * XBUF, OFF_PH + ((tile - 1) & 1) * PBUF);

        // ---- phase A (HMMA): scores from XH[bcur] ----
        float c[2][2][4];
        #pragma unroll
        for (int m = 0; m < 2; ++m)
            #pragma unroll
            for (int n = 0; n < 2; ++n)
                c[m][n][0] = c[m][n][1] = c[m][n][2] = c[m][n][3] = 0.f;
        const int xcur = OFF_XH + bcur * XBUF;
        #pragma unroll
        for (int k = 0; k < 8; ++k) {
            uint32_t bf[2][2];
            #pragma unroll
            for (int n = 0; n < 2; ++n)
                ldsm_x2(bf[n], sb + xcur + (wsb + n * 8 + (lane & 7)) * PITCH
                               + (k * 2 + ((lane >> 3) & 1)) * 16);
            #pragma unroll
            for (int m = 0; m < 2; ++m)
                #pragma unroll
                for (int n = 0; n < 2; ++n)
                    mma16816(c[m][n], qa[m][k], bf[n]);
        }

        // ---- epilogue: mask+exp, p -> fp16 in PH[tile&1], lsum in regs ----
        {
            const int pcur = OFF_PH + (tile & 1) * PBUF;
            uchar2 mv[2];
            #pragma unroll
            for (int n = 0; n < 2; ++n)
                mv[n] = *reinterpret_cast<const uchar2*>(
                    m8 + tile * TS + wsb + n * 8 + scol);
            #pragma unroll
            for (int m = 0; m < 2; ++m)
                #pragma unroll
                for (int h = 0; h < 2; ++h) {
                    int q = m * 16 + h * 8 + g;
                    if (q < kNQ) {
                        float la = 0.f;
                        #pragma unroll
                        for (int n = 0; n < 2; ++n) {
                            float e0 = mv[n].x ? __expf(c[m][n][h * 2 + 0]) : 0.f;
                            float e1 = mv[n].y ? __expf(c[m][n][h * 2 + 1]) : 0.f;
                            la += e0 + e1;
                            *reinterpret_cast<uint32_t*>(
                                smem + pcur + q * PITCH + (wsb + n * 8 + scol) * 2)
                                = h2u(__floats2half2_rn(e0, e1));
                        }
                        lsum[m * 2 + h] += la;
                    }
                }
        }

        // ---- convert next tile into XH[bnxt]; prefetch tile+2 ----
        if (tile + 1 < NTILE) convert(OFF_XH + bnxt * XBUF);
        if (tile + 2 < NTILE) {
            const float4* src = xb4 + (tile + 2) * (TS * 32);
            #pragma unroll
            for (int i = 0; i < 16; ++i) xpre[i] = src[t + i * THREADS];
        }
        __syncthreads();     // the ONLY barrier per tile

        bprev = bcur; bcur = bnxt; bnxt = (bnxt + 1 == 3) ? 0 : bnxt + 1;
    }
    // final phase B (tile 15): XH[15%3], PH[15&1]
    phaseB(OFF_XH + bprev * XBUF, OFF_PH + ((NTILE - 1) & 1) * PBUF);

    // ---- reduce lsum across lane-quads, per-warp stash, invert ----
    #pragma unroll
    for (int o = 1; o < 4; o <<= 1)
        #pragma unroll
        for (int v = 0; v < 4; ++v)
            lsum[v] += __shfl_xor_sync(0xffffffffu, lsum[v], o);
    if ((lane & 3) == 0) {
        lr[w * 32 + g]      = lsum[0];
        lr[w * 32 + 8 + g]  = lsum[1];
        lr[w * 32 + 16 + g] = lsum[2];
        lr[w * 32 + 24 + g] = lsum[3];
    }
    __syncthreads();
    if (t < kNQ) {
        float s = 0.f;
        #pragma unroll
        for (int r = 0; r < 8; ++r) s += lr[r * 32 + t];
        li[t] = 1.0f / s;
    }
    __syncthreads();

    // ---- store output directly from C-fragments ----
    float* ob = out + (size_t)b * OUT_PER_B;
    #pragma unroll
    for (int m = 0; m < 2; ++m)
        #pragma unroll
        for (int h = 0; h < 2; ++h) {
            int q = m * 16 + h * 8 + g;
            if (q < kNQ) {
                float inv = li[q];
                #pragma unroll
                for (int n = 0; n < 2; ++n) {
                    int d = wsb + n * 8 + scol;
                    *reinterpret_cast<float2*>(ob + q * kD + d) =
                        make_float2(co[m][n][h * 2] * inv, co[m][n][h * 2 + 1] * inv);
                }
            }
        }
}

extern "C" void kernel_launch(void* const* d_in, const int* in_sizes, int n_in,
                              void* d_out, int out_size) {
    const float* x    = (const float*)d_in[0];
    const float* qe   = (const float*)d_in[1];
    const int*   ques = (const int*)d_in[2];
    const int*   mask = (const int*)d_in[3];
    float* out = (float*)d_out;

    cudaFuncSetAttribute(AttentionPooling_main,
                         cudaFuncAttributeMaxDynamicSharedMemorySize, SMEM_BYTES);
    AttentionPooling_main<<<kB, THREADS, SMEM_BYTES>>>(x, qe, ques, mask, out);
}

// round 14
// speedup vs baseline: 2.7634x; 1.0545x over previous
#include <cuda_runtime.h>
#include <cuda_fp16.h>
#include <cstdint>

namespace {
constexpr int kB = 128, kS = 2048, kD = 128, kNQ = 18;
constexpr int TS = 128, THREADS = 256;
constexpr int HALF_S = kS / 2, NTILE = HALF_S / TS;   // 1024, 8
constexpr float SCALE = 0.08838834764831845f;   // 1/sqrt(128)
constexpr int PITCH = 272;                      // fp16 row pitch
constexpr int XBUF  = TS * PITCH;               // 34816 B per XH buffer

constexpr int OFF_XH = 0;                       // x fp16 [2][128][272]
constexpr int OFF_Q  = OFF_XH + 2 * XBUF;       // 69632: q fp16 [32][272]
constexpr int OFF_PH = OFF_Q + 32 * PITCH;      // 78336: p fp16 [32][272]
constexpr int OFF_LR = OFF_PH + 32 * PITCH;     // 87040
constexpr int OFF_LI = OFF_LR + 1024;           // 88064
constexpr int OFF_MB = OFF_LI + 128;            // 88192: mask bytes (1KB)
constexpr int SMEM_BYTES = OFF_MB + 1024;       // 89216 -> 2 CTAs/SM
constexpr int OUT_PER_B = kNQ * kD;
}

__device__ float    g_partP[kB][2][OUT_PER_B];
__device__ float    g_partL[kB][2][kNQ];
__device__ unsigned g_cnt[kB];

__device__ __forceinline__ void ldsm_x4(uint32_t* r, uint32_t a) {
    asm volatile("ldmatrix.sync.aligned.m8n8.x4.shared.b16 {%0,%1,%2,%3},[%4];"
        : "=r"(r[0]), "=r"(r[1]), "=r"(r[2]), "=r"(r[3]) : "r"(a));
}
__device__ __forceinline__ void ldsm_x2(uint32_t* r, uint32_t a) {
    asm volatile("ldmatrix.sync.aligned.m8n8.x2.shared.b16 {%0,%1},[%2];"
        : "=r"(r[0]), "=r"(r[1]) : "r"(a));
}
__device__ __forceinline__ void ldsm_x2t(uint32_t* r, uint32_t a) {
    asm volatile("ldmatrix.sync.aligned.m8n8.x2.trans.shared.b16 {%0,%1},[%2];"
        : "=r"(r[0]), "=r"(r[1]) : "r"(a));
}
__device__ __forceinline__ void mma16816(float* c, const uint32_t* a, const uint32_t* b) {
    asm volatile("mma.sync.aligned.m16n8k16.row.col.f32.f16.f16.f32 "
        "{%0,%1,%2,%3},{%4,%5,%6,%7},{%8,%9},{%0,%1,%2,%3};"
        : "+f"(c[0]), "+f"(c[1]), "+f"(c[2]), "+f"(c[3])
        : "r"(a[0]), "r"(a[1]), "r"(a[2]), "r"(a[3]), "r"(b[0]), "r"(b[1]));
}
__device__ __forceinline__ uint32_t h2u(__half2 h) {
    uint32_t u; *reinterpret_cast<__half2*>(&u) = h; return u;
}

__global__ void __launch_bounds__(THREADS, 2)
AttentionPooling_main(const float* __restrict__ x,
                      const float* __restrict__ qe,
                      const int*   __restrict__ ques,
                      const int*   __restrict__ mask,
                      float*       __restrict__ out)
{
    extern __shared__ char smem[];
    float*   lr = reinterpret_cast<float*>(smem + OFF_LR);
    float*   li = reinterpret_cast<float*>(smem + OFF_LI);
    uint8_t* m8 = reinterpret_cast<uint8_t*>(smem + OFF_MB);
    __shared__ int s_flag;

    const int t = threadIdx.x, w = t >> 5, lane = t & 31;
    const int b = blockIdx.x >> 1, half = blockIdx.x & 1;
    const int wsb = w * 16;
    const int g = lane >> 2, scol = (lane & 3) * 2;
    const uint32_t sb = (uint32_t)__cvta_generic_to_shared(smem);

    const float4* xb4 = reinterpret_cast<const float4*>(
        x + (size_t)b * kS * kD + (size_t)half * HALF_S * kD);

    float4 xpre[8];
    auto ldg_half = [&](int tile, int h) {
        const float4* src = xb4 + tile * (TS * 32) + h * 2048;
        #pragma unroll
        for (int i = 0; i < 8; ++i) xpre[i] = src[t + i * THREADS];
    };
    auto conv_half = [&](int xbase, int h) {
        #pragma unroll
        for (int i = 0; i < 8; ++i) {
            float4 a = xpre[i];
            int s = w + i * 8 + h * 64;
            uint2 ph = make_uint2(h2u(__floats2half2_rn(a.x, a.y)),
                                  h2u(__floats2half2_rn(a.z, a.w)));
            *reinterpret_cast<uint2*>(smem + xbase + s * PITCH + lane * 8) = ph;
        }
    };

    ldg_half(0, 0);

    // ---- mask half -> bytes ----
    for (int i = t; i < HALF_S / 4; i += THREADS) {
        int4 mv = reinterpret_cast<const int4*>(mask + b * kS + half * HALF_S)[i];
        uint32_t pk = (mv.x & 1) | ((mv.y & 1) << 8) |
                      ((mv.z & 1) << 16) | ((mv.w & 1) << 24);
        *reinterpret_cast<uint32_t*>(m8 + i * 4) = pk;
    }
    // ---- q gather: fp16 [32][272], rows >= kNQ zeroed ----
    for (int i = t; i < 32 * 16; i += THREADS) {
        int j = i >> 4, c = i & 15;
        uint4 pk = make_uint4(0u, 0u, 0u, 0u);
        if (j < kNQ) {
            int qi = ques[b * kNQ + j];
            const float4* qr = reinterpret_cast<const float4*>(qe + qi * kD);
            float4 v0 = qr[c * 2], v1 = qr[c * 2 + 1];
            pk.x = h2u(__floats2half2_rn(v0.x * SCALE, v0.y * SCALE));
            pk.y = h2u(__floats2half2_rn(v0.z * SCALE, v0.w * SCALE));
            pk.z = h2u(__floats2half2_rn(v1.x * SCALE, v1.y * SCALE));
            pk.w = h2u(__floats2half2_rn(v1.z * SCALE, v1.w * SCALE));
        }
        *reinterpret_cast<uint4*>(smem + OFF_Q + j * PITCH + c * 16) = pk;
    }
    // ---- zero PH rows 18..31 ----
    for (int i = t; i < 14 * 17; i += THREADS) {
        int r = i / 17, c = i % 17;
        *reinterpret_cast<uint4*>(smem + OFF_PH + (18 + r) * PITCH + c * 16)
            = make_uint4(0u, 0u, 0u, 0u);
    }

    float co[2][2][4];
    #pragma unroll
    for (int m = 0; m < 2; ++m)
        #pragma unroll
        for (int n = 0; n < 2; ++n)
            co[m][n][0] = co[m][n][1] = co[m][n][2] = co[m][n][3] = 0.f;
    float lsum[4] = {0.f, 0.f, 0.f, 0.f};

    // prologue: conv half1 of tile 0 into XH[0]; start ldg half2(0)
    conv_half(OFF_XH, 0);
    ldg_half(0, 1);

    for (int tile = 0; tile < NTILE; ++tile) {
        const int xcur = OFF_XH + (tile & 1) * XBUF;
        const int xnxt = OFF_XH + ((tile + 1) & 1) * XBUF;

        // finish tile's XH (rows 64..127); start ldg half1(t+1)
        conv_half(xcur, 1);
        if (tile + 1 < NTILE) ldg_half(tile + 1, 0);
        __syncthreads();

        // ---- phase A: scores[32q x 16s] from XH[xcur], qa reloaded ----
        float c[2][2][4];
        #pragma unroll
        for (int m = 0; m < 2; ++m)
            #pragma unroll
            for (int n = 0; n < 2; ++n)
                c[m][n][0] = c[m][n][1] = c[m][n][2] = c[m][n][3] = 0.f;
        #pragma unroll
        for (int k = 0; k < 8; ++k) {
            uint32_t qa[2][4], bf[2][2];
            #pragma unroll
            for (int m = 0; m < 2; ++m)
                ldsm_x4(qa[m], sb + OFF_Q + (m * 16 + (lane & 15)) * PITCH
                               + (k * 2 + (lane >> 4)) * 16);
            #pragma unroll
            for (int n = 0; n < 2; ++n)
                ldsm_x2(bf[n], sb + xcur + (wsb + n * 8 + (lane & 7)) * PITCH
                               + (k * 2 + ((lane >> 3) & 1)) * 16);
            #pragma unroll
            for (int m = 0; m < 2; ++m)
                #pragma unroll
                for (int n = 0; n < 2; ++n)
                    mma16816(c[m][n], qa[m], bf[n]);
        }

        // ---- epilogue: mask+exp -> PH, lsum in regs ----
        {
            uchar2 mv[2];
            #pragma unroll
            for (int n = 0; n < 2; ++n)
                mv[n] = *reinterpret_cast<const uchar2*>(
                    m8 + tile * TS + wsb + n * 8 + scol);
            #pragma unroll
            for (int m = 0; m < 2; ++m)
                #pragma unroll
                for (int h = 0; h < 2; ++h) {
                    int q = m * 16 + h * 8 + g;
                    if (q < kNQ) {
                        float la = 0.f;
                        #pragma unroll
                        for (int n = 0; n < 2; ++n) {
                            float e0 = mv[n].x ? __expf(c[m][n][h * 2 + 0]) : 0.f;
                            float e1 = mv[n].y ? __expf(c[m][n][h * 2 + 1]) : 0.f;
                            la += e0 + e1;
                            *reinterpret_cast<uint32_t*>(
                                smem + OFF_PH + q * PITCH + (wsb + n * 8 + scol) * 2)
                                = h2u(__floats2half2_rn(e0, e1));
                        }
                        lsum[m * 2 + h] += la;
                    }
                }
        }

        // conv half1 of next tile into XH[xnxt]; start ldg half2(t+1)
        if (tile + 1 < NTILE) { conv_half(xnxt, 0); ldg_half(tile + 1, 1); }
        __syncthreads();

        // ---- phase B: co += p . x from XH[xcur]/PH ----
        #pragma unroll
        for (int k = 0; k < 8; ++k) {
            uint32_t ah[2][4], bh[2][2];
            #pragma unroll
            for (int m = 0; m < 2; ++m)
                ldsm_x4(ah[m], sb + OFF_PH + (m * 16 + (lane & 15)) * PITCH
                               + k * 32 + (lane >> 4) * 16);
            #pragma unroll
            for (int n = 0; n < 2; ++n)
                ldsm_x2t(bh[n], sb + xcur + (k * 16 + (lane & 7)
                               + ((lane >> 3) & 1) * 8) * PITCH + (wsb + n * 8) * 2);
            #pragma unroll
            for (int m = 0; m < 2; ++m)
                #pragma unroll
                for (int n = 0; n < 2; ++n)
                    mma16816(co[m][n], ah[m], bh[n]);
        }
    }

    // ---- lsum: quad-reduce, stash, per-q sum ----
    #pragma unroll
    for (int o = 1; o < 4; o <<= 1)
        #pragma unroll
        for (int v = 0; v < 4; ++v)
            lsum[v] += __shfl_xor_sync(0xffffffffu, lsum[v], o);
    if ((lane & 3) == 0) {
        lr[w * 32 + g]      = lsum[0];
        lr[w * 32 + 8 + g]  = lsum[1];
        lr[w * 32 + 16 + g] = lsum[2];
        lr[w * 32 + 24 + g] = lsum[3];
    }
    __syncthreads();
    if (t < kNQ) {
        float s = 0.f;
        #pragma unroll
        for (int r = 0; r < 8; ++r) s += lr[r * 32 + t];
        g_partL[b][half][t] = s;
    }

    // ---- write unnormalized partial output ----
    float* P = g_partP[b][half];
    #pragma unroll
    for (int m = 0; m < 2; ++m)
        #pragma unroll
        for (int h = 0; h < 2; ++h) {
            int q = m * 16 + h * 8 + g;
            if (q < kNQ) {
                #pragma unroll
                for (int n = 0; n < 2; ++n) {
                    int d = wsb + n * 8 + scol;
                    *reinterpret_cast<float2*>(P + q * kD + d) =
                        make_float2(co[m][n][h * 2], co[m][n][h * 2 + 1]);
                }
            }
        }
    __syncthreads();

    // ---- last-arriver combines (R5-proven; counter self-resets) ----
    if (t == 0) {
        __threadfence();
        s_flag = (int)atomicAdd(&g_cnt[b], 1u);
    }
    __syncthreads();
    if (s_flag == 1) {
        __threadfence();
        if (t < kNQ)
            li[t] = 1.0f / (g_partL[b][0][t] + g_partL[b][1][t]);
        __syncthreads();
        const float* P0 = g_partP[b][0];
        const float* P1 = g_partP[b][1];
        float* ob = out + (size_t)b * OUT_PER_B;
        for (int o = t; o < OUT_PER_B; o += THREADS)
            ob[o] = (P0[o] + P1[o]) * li[o >> 7];
        if (t == 0) g_cnt[b] = 0;
    }
}

extern "C" void kernel_launch(void* const* d_in, const int* in_sizes, int n_in,
                              void* d_out, int out_size) {
    const float* x    = (const float*)d_in[0];
    const float* qe   = (const float*)d_in[1];
    const int*   ques = (const int*)d_in[2];
    const int*   mask = (const int*)d_in[3];
    float* out = (float*)d_out;

    cudaFuncSetAttribute(AttentionPooling_main,
                         cudaFuncAttributeMaxDynamicSharedMemorySize, SMEM_BYTES);
    AttentionPooling_main<<<2 * kB, THREADS, SMEM_BYTES>>>(x, qe, ques, mask, out);
}

// round 15
// speedup vs baseline: 2.7847x; 1.0077x over previous
#include <cuda_runtime.h>
#include <cuda_fp16.h>
#include <cstdint>

namespace {
constexpr int kB = 128, kS = 2048, kD = 128, kNQ = 18;
constexpr int TS = 128, NTILE = kS / TS, THREADS = 256;
constexpr float SCALE = 0.08838834764831845f;   // 1/sqrt(128)
constexpr int PITCH = 272;                      // fp16 row pitch
constexpr int XBUF  = TS * PITCH;               // 34816 B

constexpr int OFF_XH = 0;                       // x fp16 [2][128][272]
constexpr int OFF_Q  = OFF_XH + 2 * XBUF;       // 69632: q fp16 [32][272]
constexpr int OFF_LR = OFF_Q + 32 * PITCH;      // 78336: per-warp q row sums (512B)
constexpr int OFF_LI = OFF_LR + 512;            // 78848: inv sums (128B)
constexpr int OFF_MB = OFF_LI + 128;            // 78976: mask bytes (2KB)
constexpr int SMEM_BYTES = OFF_MB + 2048;       // 81024
constexpr int OUT_PER_B = kNQ * kD;
}

__device__ __forceinline__ void ldsm_x4(uint32_t* r, uint32_t a) {
    asm volatile("ldmatrix.sync.aligned.m8n8.x4.shared.b16 {%0,%1,%2,%3},[%4];"
        : "=r"(r[0]), "=r"(r[1]), "=r"(r[2]), "=r"(r[3]) : "r"(a));
}
__device__ __forceinline__ void ldsm_x2(uint32_t* r, uint32_t a) {
    asm volatile("ldmatrix.sync.aligned.m8n8.x2.shared.b16 {%0,%1},[%2];"
        : "=r"(r[0]), "=r"(r[1]) : "r"(a));
}
__device__ __forceinline__ void ldsm_x2t(uint32_t* r, uint32_t a) {
    asm volatile("ldmatrix.sync.aligned.m8n8.x2.trans.shared.b16 {%0,%1},[%2];"
        : "=r"(r[0]), "=r"(r[1]) : "r"(a));
}
__device__ __forceinline__ void mma16816(float* c, const uint32_t* a, const uint32_t* b) {
    asm volatile("mma.sync.aligned.m16n8k16.row.col.f32.f16.f16.f32 "
        "{%0,%1,%2,%3},{%4,%5,%6,%7},{%8,%9},{%0,%1,%2,%3};"
        : "+f"(c[0]), "+f"(c[1]), "+f"(c[2]), "+f"(c[3])
        : "r"(a[0]), "r"(a[1]), "r"(a[2]), "r"(a[3]), "r"(b[0]), "r"(b[1]));
}
__device__ __forceinline__ uint32_t h2u(__half2 h) {
    uint32_t u; *reinterpret_cast<__half2*>(&u) = h; return u;
}

__global__ void __launch_bounds__(THREADS, 1)
AttentionPooling_main(const float* __restrict__ x,
                      const float* __restrict__ qe,
                      const int*   __restrict__ ques,
                      const int*   __restrict__ mask,
                      float*       __restrict__ out)
{
    extern __shared__ char smem[];
    float*   lr = reinterpret_cast<float*>(smem + OFF_LR);
    float*   li = reinterpret_cast<float*>(smem + OFF_LI);
    uint8_t* m8 = reinterpret_cast<uint8_t*>(smem + OFF_MB);

    const int t = threadIdx.x, w = t >> 5, lane = t & 31;
    const int b = blockIdx.x;
    const int qh = w >> 2;                      // q-half (0/1): rows qh*16..+15
    const int sg = w & 3;                       // s-group of 32 within 128-tile
    const int g = lane >> 2, scol = (lane & 3) * 2;
    const uint32_t sb = (uint32_t)__cvta_generic_to_shared(smem);

    const float4* xb4 = reinterpret_cast<const float4*>(x + (size_t)b * kS * kD);

    // ---- prefetch FULL x tile 0 ----
    float4 xpre[16];
    #pragma unroll
    for (int i = 0; i < 16; ++i) xpre[i] = xb4[t + i * THREADS];

    // ---- mask -> bytes ----
    for (int i = t; i < kS / 4; i += THREADS) {
        int4 mv = reinterpret_cast<const int4*>(mask + b * kS)[i];
        uint32_t pk = (mv.x & 1) | ((mv.y & 1) << 8) |
                      ((mv.z & 1) << 16) | ((mv.w & 1) << 24);
        *reinterpret_cast<uint32_t*>(m8 + i * 4) = pk;
    }
    // ---- q gather: fp16 [32][272], rows >= kNQ zeroed ----
    for (int i = t; i < 32 * 16; i += THREADS) {
        int j = i >> 4, c = i & 15;
        uint4 pk = make_uint4(0u, 0u, 0u, 0u);
        if (j < kNQ) {
            int qi = ques[b * kNQ + j];
            const float4* qr = reinterpret_cast<const float4*>(qe + qi * kD);
            float4 v0 = qr[c * 2], v1 = qr[c * 2 + 1];
            pk.x = h2u(__floats2half2_rn(v0.x * SCALE, v0.y * SCALE));
            pk.y = h2u(__floats2half2_rn(v0.z * SCALE, v0.w * SCALE));
            pk.z = h2u(__floats2half2_rn(v1.x * SCALE, v1.y * SCALE));
            pk.w = h2u(__floats2half2_rn(v1.z * SCALE, v1.w * SCALE));
        }
        *reinterpret_cast<uint4*>(smem + OFF_Q + j * PITCH + c * 16) = pk;
    }
    __syncthreads();

    // ---- hoist q A-fragments for own q-half (m16): 32 regs ----
    uint32_t qa[8][4];
    #pragma unroll
    for (int k = 0; k < 8; ++k)
        ldsm_x4(qa[k], sb + OFF_Q + (qh * 16 + (lane & 15)) * PITCH
                       + (k * 2 + (lane >> 4)) * 16);

    // convert helper: xpre -> fp16 into XH buffer (full tile)
    auto convert = [&](int xbase) {
        #pragma unroll
        for (int i = 0; i < 16; ++i) {
            float4 a = xpre[i];
            int s = w + i * 8;
            uint2 ph = make_uint2(h2u(__floats2half2_rn(a.x, a.y)),
                                  h2u(__floats2half2_rn(a.z, a.w)));
            *reinterpret_cast<uint2*>(smem + xbase + s * PITCH + lane * 8) = ph;
        }
    };

    // persistent partial output: own q-half x all 128 d, over own s-groups
    float co[16][4];
    #pragma unroll
    for (int j = 0; j < 16; ++j)
        co[j][0] = co[j][1] = co[j][2] = co[j][3] = 0.f;
    float lsum0 = 0.f, lsum1 = 0.f;

    // prologue: convert tile0 -> buf0; prefetch tile1
    convert(OFF_XH);
    {
        const float4* src = xb4 + 1 * (TS * 32);
        #pragma unroll
        for (int i = 0; i < 16; ++i) xpre[i] = src[t + i * THREADS];
    }
    __syncthreads();

    for (int tile = 0; tile < NTILE; ++tile) {
        const int xcur = OFF_XH + (tile & 1) * XBUF;

        // ---- phase A: scores[16q x 32s own group] ----
        float c[4][4];
        #pragma unroll
        for (int j = 0; j < 4; ++j)
            c[j][0] = c[j][1] = c[j][2] = c[j][3] = 0.f;
        #pragma unroll
        for (int k = 0; k < 8; ++k) {
            uint32_t bf[4][2];
            #pragma unroll
            for (int n = 0; n < 4; ++n)
                ldsm_x2(bf[n], sb + xcur + (sg * 32 + n * 8 + (lane & 7)) * PITCH
                               + (k * 2 + ((lane >> 3) & 1)) * 16);
            #pragma unroll
            for (int n = 0; n < 4; ++n)
                mma16816(c[n], qa[k], bf[n]);
        }

        // ---- epilogue in registers: mask+exp -> p A-fragments ----
        uint32_t pa[2][4];
        #pragma unroll
        for (int n = 0; n < 4; ++n) {
            uchar2 mv = *reinterpret_cast<const uchar2*>(
                m8 + tile * TS + sg * 32 + n * 8 + scol);
            float e0 = mv.x ? __expf(c[n][0]) : 0.f;   // (g,   s0)
            float e1 = mv.y ? __expf(c[n][1]) : 0.f;   // (g,   s0+1)
            float e2 = mv.x ? __expf(c[n][2]) : 0.f;   // (g+8, s0)
            float e3 = mv.y ? __expf(c[n][3]) : 0.f;   // (g+8, s0+1)
            lsum0 += e0 + e1; lsum1 += e2 + e3;
            pa[n >> 1][(n & 1) * 2 + 0] = h2u(__floats2half2_rn(e0, e1));
            pa[n >> 1][(n & 1) * 2 + 1] = h2u(__floats2half2_rn(e2, e3));
        }

        // ---- phase B: co[16q x 128d] += p(own 32s) . x, A in regs ----
        #pragma unroll
        for (int kk = 0; kk < 2; ++kk) {
            #pragma unroll
            for (int j2 = 0; j2 < 16; ++j2) {
                uint32_t bh[2];
                ldsm_x2t(bh, sb + xcur + (sg * 32 + kk * 16 + (lane & 7)
                             + ((lane >> 3) & 1) * 8) * PITCH + (j2 * 8) * 2);
                mma16816(co[j2], pa[kk], bh);
            }
        }

        // ---- convert next tile; prefetch tile+2 ----
        if (tile + 1 < NTILE) convert(OFF_XH + ((tile + 1) & 1) * XBUF);
        if (tile + 2 < NTILE) {
            const float4* src = xb4 + (tile + 2) * (TS * 32);
            #pragma unroll
            for (int i = 0; i < 16; ++i) xpre[i] = src[t + i * THREADS];
        }
        __syncthreads();     // one barrier per tile
    }

    // ---- row sums: quad-reduce, stash per warp ----
    #pragma unroll
    for (int o = 1; o < 4; o <<= 1) {
        lsum0 += __shfl_xor_sync(0xffffffffu, lsum0, o);
        lsum1 += __shfl_xor_sync(0xffffffffu, lsum1, o);
    }
    if ((lane & 3) == 0) {
        lr[w * 16 + g]     = lsum0;
        lr[w * 16 + 8 + g] = lsum1;
    }

    // ---- stash co partials in smem (reuse XH area): red[w][16q][128d] ----
    float* red = reinterpret_cast<float*>(smem);
    __syncthreads();
    #pragma unroll
    for (int j2 = 0; j2 < 16; ++j2) {
        int d = j2 * 8 + scol;
        *reinterpret_cast<float2*>(red + (w * 16 + g) * 128 + d) =
            make_float2(co[j2][0], co[j2][1]);
        *reinterpret_cast<float2*>(red + (w * 16 + 8 + g) * 128 + d) =
            make_float2(co[j2][2], co[j2][3]);
    }
    __syncthreads();

    if (t < 32) {
        int hq = t >> 4, ql = t & 15;
        float s = 0.f;
        #pragma unroll
        for (int r = 0; r < 4; ++r) s += lr[(hq * 4 + r) * 16 + ql];
        li[t] = 1.0f / s;
    }
    __syncthreads();

    // ---- final: sum 4 s-group partials, normalize, store ----
    float* ob = out + (size_t)b * OUT_PER_B;
    #pragma unroll
    for (int o = t; o < 2 * 16 * 128; o += THREADS) {
        int hq = o >> 11, ql = (o >> 7) & 15, d = o & 127;
        int q = hq * 16 + ql;
        if (q < kNQ) {
            float s = 0.f;
            #pragma unroll
            for (int r = 0; r < 4; ++r)
                s += red[((hq * 4 + r) * 16 + ql) * 128 + d];
            ob[q * kD + d] = s * li[q];
        }
    }
}

extern "C" void kernel_launch(void* const* d_in, const int* in_sizes, int n_in,
                              void* d_out, int out_size) {
    const float* x    = (const float*)d_in[0];
    const float* qe   = (const float*)d_in[1];
    const int*   ques = (const int*)d_in[2];
    const int*   mask = (const int*)d_in[3];
    float* out = (float*)d_out;

    cudaFuncSetAttribute(AttentionPooling_main,
                         cudaFuncAttributeMaxDynamicSharedMemorySize, SMEM_BYTES);
    AttentionPooling_main<<<kB, THREADS, SMEM_BYTES>>>(x, qe, ques, mask, out);
}